// round 1
// baseline (speedup 1.0000x reference)
#include <cuda_runtime.h>
#include <cuda_bf16.h>
#include <cstdint>

// Problem constants
#define NN      100000
#define IN_DIM  512
#define HIDDEN  128
#define NCLS    64
#define NEDGE   3200000

// Scratch ping-pong buffers ( __device__ globals: allocation-free )
__device__ float g_bufA[(size_t)NN * NCLS];
__device__ float g_bufB[(size_t)NN * NCLS];

// ---------------------------------------------------------------------------
// Fused dense phase: out[N,64] = relu(X[N,512] @ W0[512,128]) @ W1[128,64]
// Block: 128 rows. Phase 1: 128x128 tile GEMM (BK=16), 256 threads, 8x8/thread.
// Phase 2: tile (in smem, transposed) @ W1 -> 128x64, 8x4/thread.
// ---------------------------------------------------------------------------
#define BM 128
#define BK 16

// smem layout (floats):
//   phase1: As[16][136] at 0 (2176), Bs[16][128] at 2176 (2048)
//   phase2: Ht[128][132] at 0 (16896)  -- overlaps As/Bs (sync-separated)
//   W1s[128][64] at 16896 (8192), loaded once at block start
#define AS_OFF   0
#define AS_PITCH 136
#define BS_OFF   2176
#define HT_OFF   0
#define HT_PITCH 132
#define W1_OFF   16896
#define SMEM_FLOATS (16896 + 8192)
#define SMEM_BYTES  (SMEM_FLOATS * 4)

__global__ void gemm_fused(const float* __restrict__ X,
                           const float* __restrict__ W0,
                           const float* __restrict__ W1,
                           float* __restrict__ out)
{
    extern __shared__ float sm[];
    float* As  = sm + AS_OFF;
    float* Bs  = sm + BS_OFF;
    float* Ht  = sm + HT_OFF;
    float* W1s = sm + W1_OFF;

    const int tid = threadIdx.x;
    const int bm  = blockIdx.x * BM;

    // Load W1 (128x64 fp32 = 2048 float4) once
    {
        const float4* w1v = (const float4*)W1;
        float4* w1sv = (float4*)W1s;
        #pragma unroll
        for (int i = 0; i < 8; i++)
            w1sv[tid + i * 256] = w1v[tid + i * 256];
    }

    // Phase-1 thread mapping: 16x16 thread grid of 8x8 micro-tiles
    const int tr = tid >> 4;        // 0..15 -> rows tr*8
    const int tc = tid & 15;        // 0..15 -> cols tc*4 and 64+tc*4
    const int r0 = tr * 8;
    const int c0 = tc * 4;
    const int c1 = 64 + tc * 4;

    // A-load mapping: row = tid>>2 (+pass*64), k4 = (tid&3)*4
    const int a_row = tid >> 2;
    const int a_k4  = (tid & 3) * 4;
    int grow0 = bm + a_row;       if (grow0 >= NN) grow0 = NN - 1;
    int grow1 = bm + a_row + 64;  if (grow1 >= NN) grow1 = NN - 1;

    float acc[8][8];
    #pragma unroll
    for (int i = 0; i < 8; i++)
        #pragma unroll
        for (int j = 0; j < 8; j++) acc[i][j] = 0.f;

    // prologue: prefetch tile 0
    float4 pa0 = *(const float4*)&X[(size_t)grow0 * IN_DIM + a_k4];
    float4 pa1 = *(const float4*)&X[(size_t)grow1 * IN_DIM + a_k4];
    // B: flat float4 idx f = tid + h*256 ; k = f>>5, c4 = (f&31)*4
    float4 pb0 = *(const float4*)&W0[(size_t)(tid >> 5) * HIDDEN + (tid & 31) * 4];
    float4 pb1 = *(const float4*)&W0[(size_t)(((tid + 256) >> 5)) * HIDDEN + ((tid + 256) & 31) * 4];

    const int NKT = IN_DIM / BK;   // 32
    for (int kt = 0; kt < NKT; kt++) {
        // store prefetched tile to smem
        As[(a_k4 + 0) * AS_PITCH + a_row] = pa0.x;
        As[(a_k4 + 1) * AS_PITCH + a_row] = pa0.y;
        As[(a_k4 + 2) * AS_PITCH + a_row] = pa0.z;
        As[(a_k4 + 3) * AS_PITCH + a_row] = pa0.w;
        As[(a_k4 + 0) * AS_PITCH + a_row + 64] = pa1.x;
        As[(a_k4 + 1) * AS_PITCH + a_row + 64] = pa1.y;
        As[(a_k4 + 2) * AS_PITCH + a_row + 64] = pa1.z;
        As[(a_k4 + 3) * AS_PITCH + a_row + 64] = pa1.w;
        *(float4*)&Bs[(tid >> 5) * HIDDEN + (tid & 31) * 4] = pb0;
        *(float4*)&Bs[((tid + 256) >> 5) * HIDDEN + ((tid + 256) & 31) * 4] = pb1;
        __syncthreads();

        if (kt + 1 < NKT) {
            const int kb = (kt + 1) * BK;
            pa0 = *(const float4*)&X[(size_t)grow0 * IN_DIM + kb + a_k4];
            pa1 = *(const float4*)&X[(size_t)grow1 * IN_DIM + kb + a_k4];
            pb0 = *(const float4*)&W0[(size_t)(kb + (tid >> 5)) * HIDDEN + (tid & 31) * 4];
            pb1 = *(const float4*)&W0[(size_t)(kb + ((tid + 256) >> 5)) * HIDDEN + ((tid + 256) & 31) * 4];
        }

        #pragma unroll
        for (int k = 0; k < BK; k++) {
            float4 a0 = *(const float4*)&As[k * AS_PITCH + r0];
            float4 a1 = *(const float4*)&As[k * AS_PITCH + r0 + 4];
            float4 b0 = *(const float4*)&Bs[k * HIDDEN + c0];
            float4 b1 = *(const float4*)&Bs[k * HIDDEN + c1];
            float av[8] = {a0.x, a0.y, a0.z, a0.w, a1.x, a1.y, a1.z, a1.w};
            #pragma unroll
            for (int i = 0; i < 8; i++) {
                acc[i][0] += av[i] * b0.x;
                acc[i][1] += av[i] * b0.y;
                acc[i][2] += av[i] * b0.z;
                acc[i][3] += av[i] * b0.w;
                acc[i][4] += av[i] * b1.x;
                acc[i][5] += av[i] * b1.y;
                acc[i][6] += av[i] * b1.z;
                acc[i][7] += av[i] * b1.w;
            }
        }
        __syncthreads();
    }

    // ReLU + store transposed tile Ht[hidden][row]
    #pragma unroll
    for (int j = 0; j < 8; j++) {
        const int col = (j < 4) ? (c0 + j) : (c1 + j - 4);
        float4 lo, hi;
        lo.x = fmaxf(acc[0][j], 0.f); lo.y = fmaxf(acc[1][j], 0.f);
        lo.z = fmaxf(acc[2][j], 0.f); lo.w = fmaxf(acc[3][j], 0.f);
        hi.x = fmaxf(acc[4][j], 0.f); hi.y = fmaxf(acc[5][j], 0.f);
        hi.z = fmaxf(acc[6][j], 0.f); hi.w = fmaxf(acc[7][j], 0.f);
        *(float4*)&Ht[col * HT_PITCH + r0]     = lo;
        *(float4*)&Ht[col * HT_PITCH + r0 + 4] = hi;
    }
    __syncthreads();

    // Phase 2: out[r][c] = sum_k Ht[k][r] * W1s[k][c]
    const int rg = tid >> 4;   // rows rg*8
    const int cg = tid & 15;   // cols cg*4
    float acc2[8][4];
    #pragma unroll
    for (int i = 0; i < 8; i++)
        #pragma unroll
        for (int j = 0; j < 4; j++) acc2[i][j] = 0.f;

    #pragma unroll 4
    for (int k = 0; k < HIDDEN; k++) {
        float4 a0 = *(const float4*)&Ht[k * HT_PITCH + rg * 8];
        float4 a1 = *(const float4*)&Ht[k * HT_PITCH + rg * 8 + 4];
        float4 b  = *(const float4*)&W1s[k * NCLS + cg * 4];
        float av[8] = {a0.x, a0.y, a0.z, a0.w, a1.x, a1.y, a1.z, a1.w};
        #pragma unroll
        for (int i = 0; i < 8; i++) {
            acc2[i][0] += av[i] * b.x;
            acc2[i][1] += av[i] * b.y;
            acc2[i][2] += av[i] * b.z;
            acc2[i][3] += av[i] * b.w;
        }
    }

    #pragma unroll
    for (int i = 0; i < 8; i++) {
        const int m = bm + rg * 8 + i;
        if (m < NN) {
            float4 v = {acc2[i][0], acc2[i][1], acc2[i][2], acc2[i][3]};
            *(float4*)&out[(size_t)m * NCLS + cg * 4] = v;
        }
    }
}

// ---------------------------------------------------------------------------
// SpMM: y[dst] += val * x[src]  over E edges, feature dim 64.
// 16 threads per edge, each handles one float4; vector red.global.add.v4.f32.
// Each thread processes EDGE_ITER consecutive edge-groups.
// ---------------------------------------------------------------------------
#define EDGE_ITER 4

__device__ __forceinline__ void red_add_v4(float* addr, float4 v) {
    asm volatile("red.global.add.v4.f32 [%0], {%1,%2,%3,%4};"
                 :: "l"(addr), "f"(v.x), "f"(v.y), "f"(v.z), "f"(v.w)
                 : "memory");
}

__global__ void spmm_kernel(const int* __restrict__ src,
                            const int* __restrict__ dst,
                            const float* __restrict__ val,
                            const float* __restrict__ x,
                            float* __restrict__ y)
{
    const unsigned tid = blockIdx.x * blockDim.x + threadIdx.x;
    const unsigned g = tid >> 4;          // edge group
    const unsigned p = (tid & 15) * 4;    // feature offset
    unsigned e = g * EDGE_ITER;
    #pragma unroll
    for (int it = 0; it < EDGE_ITER; it++, e++) {
        if (e < NEDGE) {
            const int   s = __ldg(src + e);
            const int   d = __ldg(dst + e);
            const float v = __ldg(val + e);
            float4 xv = *(const float4*)(x + (size_t)s * NCLS + p);
            xv.x *= v; xv.y *= v; xv.z *= v; xv.w *= v;
            red_add_v4(y + (size_t)d * NCLS + p, xv);
        }
    }
}

// ---------------------------------------------------------------------------
extern "C" void kernel_launch(void* const* d_in, const int* in_sizes, int n_in,
                              void* d_out, int out_size)
{
    const float* X  = (const float*)d_in[0];
    const float* W0 = (const float*)d_in[1];
    const float* W1 = (const float*)d_in[2];
    const float* ev = (const float*)d_in[3];
    const int*   es = (const int*)d_in[4];
    const int*   ed = (const int*)d_in[5];
    float* out = (float*)d_out;

    float *bufA, *bufB;
    cudaGetSymbolAddress((void**)&bufA, g_bufA);
    cudaGetSymbolAddress((void**)&bufB, g_bufB);

    cudaFuncSetAttribute(gemm_fused, cudaFuncAttributeMaxDynamicSharedMemorySize,
                         SMEM_BYTES);

    const int gemm_grid = (NN + BM - 1) / BM;   // 782
    gemm_fused<<<gemm_grid, 256, SMEM_BYTES>>>(X, W0, W1, bufA);

    const size_t feat_bytes = (size_t)NN * NCLS * sizeof(float);
    // edges*16 threads / EDGE_ITER per thread
    const int spmm_grid = (int)(((size_t)NEDGE * 16) / (256 * EDGE_ITER)); // 50000

    cudaMemsetAsync(bufB, 0, feat_bytes);
    spmm_kernel<<<spmm_grid, 256>>>(es, ed, ev, bufA, bufB);

    cudaMemsetAsync(out, 0, feat_bytes);
    spmm_kernel<<<spmm_grid, 256>>>(es, ed, ev, bufB, out);
}